// round 13
// baseline (speedup 1.0000x reference)
#include <cuda_runtime.h>

#define T 512
#define C 6
#define R 256
#define BC 2
#define NBLK 128        // 128 CTAs x 2 batches, one wave
#define NRP 10          // reg k-pairs per warp (20 rows)
#define NSP 6           // smem k-pairs per warp (12 rows)
#define WSM_ULL (8 * NSP * 256)      // 48 rows-of-pairs x 256 r
#define REDN (8 * 2 * R)

typedef unsigned long long ull;

// Packed 2xfp32 FMA (sm_100+): d.lane += a.lane * b.lane
__device__ __forceinline__ void fma2(ull& d, ull a, ull b) {
    asm("fma.rn.f32x2 %0, %1, %2, %0;" : "+l"(d) : "l"(a), "l"(b));
}
__device__ __forceinline__ float sum2(ull a) {
    float lo, hi;
    asm("mov.b64 {%0,%1}, %2;" : "=f"(lo), "=f"(hi) : "l"(a));
    return lo + hi;
}
__device__ __forceinline__ ull pack2(float lo, float hi) {
    ull u; asm("mov.b64 %0, {%1,%2};" : "=l"(u) : "f"(lo), "f"(hi));
    return u;
}
// tanh(z) = 1 - 2/(exp(2z)+1): exp->inf gives exactly 1 (no NaN); abs err ~1e-7.
__device__ __forceinline__ float tanh_fast(float z) {
    float e = __expf(2.0f * z);
    return 1.0f - __fdividef(2.0f, e + 1.0f);
}

// R10 base + two tail optimizations:
//   (1) h NEVER touches smem: lane l of warp w owns h[32w+l] in a register
//       (it computes exactly that value in phase2), and phase1 operands are
//       built with shfl.sync from the warp's own lanes. Removes the
//       STS->syncwarp->LDS round-trip from the serial tail AND 128 wf/step
//       of crossbar traffic, paying only issue slots (issue util is 40%).
//   (2) xp (input projection) computed BEFORE the barrier: it depends only
//       on xsm/win, but the compiler could not hoist it across bar.sync.
//       Also fills the red-STS drain window at barrier entry.
//   Everything else proven in R10: warp w owns k in [32w,32w+32),
//   local pairs 0..9 in regs (160 regs), pairs 10..15 in smem (768 wf/step),
//   lane l owns outputs r(g,s) = 64g+2l+s, ping-pong red, ONE bar per step.
// smem: Wsm 96KB | red x2 32KB | xsm 24KB = 152KB
__global__ void __launch_bounds__(256, 1)
esn_kernel(const float* __restrict__ x, const float* __restrict__ W_in,
           const float* __restrict__ W_res, float* __restrict__ out)
{
    extern __shared__ char smraw[];
    ull*   Wsm  = (ull*)smraw;
    float* red0 = (float*)(Wsm + WSM_ULL);
    float* red1 = red0 + REDN;
    float* xsm  = red1 + REDN;            // [b(2)][t(512)][c(6)]

    const int tid = threadIdx.x;
    const int w = tid >> 5, l = tid & 31;
    const int b0 = blockIdx.x * BC;

    // Stage x for both batches (contiguous, float4-coalesced).
    {
        const float4* xg = (const float4*)(x + (size_t)b0 * T * C);
        float4* xs = (float4*)xsm;
        for (int m = tid; m < (BC * T * C) / 4; m += 256) xs[m] = xg[m];
    }
    // Stage smem W part, pair-packed: Wsm[sp][r] = (W[k0][r], W[k0+1][r]),
    // sp = wp*NSP + j, k0 = 32*wp + 2*NRP + 2*j.  Coalesced gmem reads (r = tid).
    for (int sp = 0; sp < 8 * NSP; ++sp) {
        int wp = sp / NSP, j = sp % NSP;
        int k0 = 32 * wp + 2 * NRP + 2 * j;
        Wsm[sp * R + tid] = pack2(W_res[k0 * R + tid], W_res[(k0 + 1) * R + tid]);
    }
    // Register part: pairs j=0..9 -> k0 = 32w + 2j, this thread's 8 r's.
    ull wreg[NRP * 8];
    #pragma unroll
    for (int j = 0; j < NRP; ++j) {
        int k0 = 32 * w + 2 * j;
        #pragma unroll
        for (int g = 0; g < 4; ++g) {
            int r0 = 64 * g + 2 * l;
            wreg[j * 8 + 2 * g + 0] = pack2(W_res[k0 * R + r0],     W_res[(k0 + 1) * R + r0]);
            wreg[j * 8 + 2 * g + 1] = pack2(W_res[k0 * R + r0 + 1], W_res[(k0 + 1) * R + r0 + 1]);
        }
    }
    float win[C];
    #pragma unroll
    for (int c = 0; c < C; ++c) win[c] = W_in[c * R + tid];

    __syncthreads();   // Wsm/xsm staged

    const ulonglong2* Wp = (const ulonglong2*)(Wsm + (size_t)w * NSP * R);
    const float2* xv0 = (const float2*)(xsm);             // batch b0
    const float2* xv1 = (const float2*)(xsm + T * C);     // batch b0+1
    float* __restrict__ o0 = out + (size_t)b0 * T * R + tid;
    float* __restrict__ o1 = out + (size_t)(b0 + 1) * T * R + tid;

    // h lives in registers: this thread (lane l of warp w) owns h[32w+l].
    float h0r = 0.0f, h1r = 0.0f;

    for (int t = 0; t < T; ++t) {
        float* redc = (t & 1) ? red1 : red0;   // ping-pong partials buffer

        // x loads issued early (latency hidden under phase1).
        float2 xa = xv0[3 * t], xb = xv0[3 * t + 1], xc = xv0[3 * t + 2];
        float2 xd = xv1[3 * t], xe = xv1[3 * t + 1], xf = xv1[3 * t + 2];

        // acc[(2g+s)*2 + b] : lanes carry (even-k, odd-k) partials for r(g,s), batch b.
        ull acc[16];
        #pragma unroll
        for (int i = 0; i < 16; ++i) acc[i] = 0;

        // ---- register part: k-pairs 0..9 = h chunks q=0..4 (shfl-built operands)
        #pragma unroll
        for (int q = 0; q < 5; ++q) {
            ulonglong2 ha, hb;
            ha.x = pack2(__shfl_sync(0xffffffffu, h0r, 4 * q + 0),
                         __shfl_sync(0xffffffffu, h0r, 4 * q + 1));
            ha.y = pack2(__shfl_sync(0xffffffffu, h0r, 4 * q + 2),
                         __shfl_sync(0xffffffffu, h0r, 4 * q + 3));
            hb.x = pack2(__shfl_sync(0xffffffffu, h1r, 4 * q + 0),
                         __shfl_sync(0xffffffffu, h1r, 4 * q + 1));
            hb.y = pack2(__shfl_sync(0xffffffffu, h1r, 4 * q + 2),
                         __shfl_sync(0xffffffffu, h1r, 4 * q + 3));
            #pragma unroll
            for (int gs = 0; gs < 8; ++gs) {
                fma2(acc[gs * 2 + 0], ha.x, wreg[(2 * q) * 8 + gs]);
                fma2(acc[gs * 2 + 1], hb.x, wreg[(2 * q) * 8 + gs]);
                fma2(acc[gs * 2 + 0], ha.y, wreg[(2 * q + 1) * 8 + gs]);
                fma2(acc[gs * 2 + 1], hb.y, wreg[(2 * q + 1) * 8 + gs]);
            }
        }
        // ---- smem part: h chunks q=5..7 (local pairs 10..15), conflict-free LDS.128
        #pragma unroll
        for (int q = 5; q < 8; ++q) {
            const int j0 = 2 * (q - 5), j1 = j0 + 1;
            ulonglong2 ha, hb;
            ha.x = pack2(__shfl_sync(0xffffffffu, h0r, 4 * q + 0),
                         __shfl_sync(0xffffffffu, h0r, 4 * q + 1));
            ha.y = pack2(__shfl_sync(0xffffffffu, h0r, 4 * q + 2),
                         __shfl_sync(0xffffffffu, h0r, 4 * q + 3));
            hb.x = pack2(__shfl_sync(0xffffffffu, h1r, 4 * q + 0),
                         __shfl_sync(0xffffffffu, h1r, 4 * q + 1));
            hb.y = pack2(__shfl_sync(0xffffffffu, h1r, 4 * q + 2),
                         __shfl_sync(0xffffffffu, h1r, 4 * q + 3));
            #pragma unroll
            for (int g = 0; g < 4; ++g) {
                ulonglong2 wA = Wp[(j0 * R + 64 * g + 2 * l) >> 1];
                ulonglong2 wB = Wp[(j1 * R + 64 * g + 2 * l) >> 1];
                fma2(acc[(2 * g + 0) * 2 + 0], ha.x, wA.x);
                fma2(acc[(2 * g + 1) * 2 + 0], ha.x, wA.y);
                fma2(acc[(2 * g + 0) * 2 + 1], hb.x, wA.x);
                fma2(acc[(2 * g + 1) * 2 + 1], hb.x, wA.y);
                fma2(acc[(2 * g + 0) * 2 + 0], ha.y, wB.x);
                fma2(acc[(2 * g + 1) * 2 + 0], ha.y, wB.y);
                fma2(acc[(2 * g + 0) * 2 + 1], hb.y, wB.x);
                fma2(acc[(2 * g + 1) * 2 + 1], hb.y, wB.y);
            }
        }

        // Publish partials: red[w][2r + b], float4 per g.
        #pragma unroll
        for (int g = 0; g < 4; ++g) {
            int r0 = 64 * g + 2 * l;
            float4 v;
            v.x = sum2(acc[(2 * g + 0) * 2 + 0]);
            v.y = sum2(acc[(2 * g + 0) * 2 + 1]);
            v.z = sum2(acc[(2 * g + 1) * 2 + 0]);
            v.w = sum2(acc[(2 * g + 1) * 2 + 1]);
            *(float4*)&redc[w * 2 * R + 2 * r0] = v;
        }

        // xp computed PRE-barrier (no dependence on red; fills STS drain window).
        float xp0 = xa.x * win[0] + xa.y * win[1] + xb.x * win[2]
                  + xb.y * win[3] + xc.x * win[4] + xc.y * win[5];
        float xp1 = xd.x * win[0] + xd.y * win[1] + xe.x * win[2]
                  + xe.y * win[3] + xf.x * win[4] + xf.y * win[5];

        __syncthreads();   // partials STS -> phase2 LDS (single bar per step)

        // ---- phase2: thread tid = r; tree-reduce 8 warps' partials.
        const float2* rp = (const float2*)&redc[2 * tid];
        float2 p0 = rp[0 * R], p1 = rp[1 * R], p2 = rp[2 * R], p3 = rp[3 * R];
        float2 p4 = rp[4 * R], p5 = rp[5 * R], p6 = rp[6 * R], p7 = rp[7 * R];
        float sx = ((p0.x + p1.x) + (p2.x + p3.x)) + ((p4.x + p5.x) + (p6.x + p7.x));
        float sy = ((p0.y + p1.y) + (p2.y + p3.y)) + ((p4.y + p5.y) + (p6.y + p7.y));

        h0r = tanh_fast(sx + xp0);   // stays in registers; next step shfl-distributes
        h1r = tanh_fast(sy + xp1);

        o0[(size_t)t * R] = h0r;     // coalesced STG (gmem; does not block bar)
        o1[(size_t)t * R] = h1r;
        // no syncwarp needed: shfl.sync at the top of next phase1 converges the warp
    }
}

extern "C" void kernel_launch(void* const* d_in, const int* in_sizes, int n_in,
                              void* d_out, int out_size) {
    const float* x     = (const float*)d_in[0];
    const float* W_in  = (const float*)d_in[1];
    const float* W_res = (const float*)d_in[2];
    float* out = (float*)d_out;

    // 96KB (Wsm) + 32KB (red x2) + 24KB (xsm) = 155648 bytes
    const size_t smem_bytes = (size_t)WSM_ULL * sizeof(ull)
                            + (size_t)2 * REDN * sizeof(float)
                            + (size_t)BC * T * C * sizeof(float);
    cudaFuncSetAttribute(esn_kernel, cudaFuncAttributeMaxDynamicSharedMemorySize,
                         (int)smem_bytes);
    esn_kernel<<<NBLK, R, smem_bytes>>>(x, W_in, W_res, out);
}

// round 14
// speedup vs baseline: 1.0525x; 1.0525x over previous
#include <cuda_runtime.h>

#define T 512
#define C 6
#define R 256
#define BC 2
#define NBLK 128        // 128 CTAs x 2 batches, one wave
#define NRP 10          // reg k-pairs per warp (20 rows)
#define NSP 6           // smem k-pairs per warp (12 rows)
#define WSM_ULL (8 * NSP * 256)      // 48 rows-of-pairs x 256 r
#define REDN (8 * 2 * R)

typedef unsigned long long ull;

// Packed 2xfp32 FMA (sm_100+): d.lane += a.lane * b.lane
__device__ __forceinline__ void fma2(ull& d, ull a, ull b) {
    asm("fma.rn.f32x2 %0, %1, %2, %0;" : "+l"(d) : "l"(a), "l"(b));
}
__device__ __forceinline__ float sum2(ull a) {
    float lo, hi;
    asm("mov.b64 {%0,%1}, %2;" : "=f"(lo), "=f"(hi) : "l"(a));
    return lo + hi;
}
__device__ __forceinline__ ull pack2(float lo, float hi) {
    ull u; asm("mov.b64 %0, {%1,%2};" : "=l"(u) : "f"(lo), "f"(hi));
    return u;
}
// tanh(z) = 1 - 2/(exp(2z)+1): exp->inf gives exactly 1 (no NaN); abs err ~1e-7.
__device__ __forceinline__ float tanh_fast(float z) {
    float e = __expf(2.0f * z);
    return 1.0f - __fdividef(2.0f, e + 1.0f);
}

// R10 (best, 498us) + xp hoist. h goes through smem (broadcast LDS is the
// cheap path on sm_103a; R13 proved shfl rides the same MIO pipe and costs
// MORE wavefronts). Structure:
//   warp w owns k in [32w, 32w+32) = k-pairs [16w, 16w+16)
//     local pairs 0..9   -> registers (wreg, 80 ull = 160 regs)
//     local pairs 10..15 -> smem Wsm (12 rows/warp: 96KB -> 768 wf/step)
//   lane l owns outputs r(g,s) = 64g + 2l + s
//   h warp-local (thread r produces h[r], consumed by warp r>>5): __syncwarp only.
//   Ping-pong red buffer -> ONE __syncthreads per step.  x staged in smem.
//   NEW: xp (input projection) computed pre-barrier — depends only on xsm/win;
//   removes ~6 LDS + 12 FFMA + add-chain from the serial post-barrier tail.
// smem: Wsm 96KB | hsm 2KB | red x2 32KB | xsm 24KB = 154KB
__global__ void __launch_bounds__(256, 1)
esn_kernel(const float* __restrict__ x, const float* __restrict__ W_in,
           const float* __restrict__ W_res, float* __restrict__ out)
{
    extern __shared__ char smraw[];
    ull*   Wsm  = (ull*)smraw;
    float* hsm  = (float*)(Wsm + WSM_ULL);
    float* red0 = hsm + 2 * R;
    float* red1 = red0 + REDN;
    float* xsm  = red1 + REDN;            // [b(2)][t(512)][c(6)]

    const int tid = threadIdx.x;
    const int w = tid >> 5, l = tid & 31;
    const int b0 = blockIdx.x * BC;

    // Stage x for both batches (contiguous, float4-coalesced).
    {
        const float4* xg = (const float4*)(x + (size_t)b0 * T * C);
        float4* xs = (float4*)xsm;
        for (int m = tid; m < (BC * T * C) / 4; m += 256) xs[m] = xg[m];
    }
    // Stage smem W part, pair-packed: Wsm[sp][r] = (W[k0][r], W[k0+1][r]),
    // sp = wp*NSP + j, k0 = 32*wp + 2*NRP + 2*j.  Coalesced gmem reads (r = tid).
    for (int sp = 0; sp < 8 * NSP; ++sp) {
        int wp = sp / NSP, j = sp % NSP;
        int k0 = 32 * wp + 2 * NRP + 2 * j;
        Wsm[sp * R + tid] = pack2(W_res[k0 * R + tid], W_res[(k0 + 1) * R + tid]);
    }
    // Register part: pairs j=0..9 -> k0 = 32w + 2j, this thread's 8 r's.
    ull wreg[NRP * 8];
    #pragma unroll
    for (int j = 0; j < NRP; ++j) {
        int k0 = 32 * w + 2 * j;
        #pragma unroll
        for (int g = 0; g < 4; ++g) {
            int r0 = 64 * g + 2 * l;
            wreg[j * 8 + 2 * g + 0] = pack2(W_res[k0 * R + r0],     W_res[(k0 + 1) * R + r0]);
            wreg[j * 8 + 2 * g + 1] = pack2(W_res[k0 * R + r0 + 1], W_res[(k0 + 1) * R + r0 + 1]);
        }
    }
    float win[C];
    #pragma unroll
    for (int c = 0; c < C; ++c) win[c] = W_in[c * R + tid];

    hsm[tid] = 0.0f; hsm[R + tid] = 0.0f;
    __syncthreads();

    // Warp-uniform h slice pointers (broadcast LDS, 1 wavefront each).
    const ulonglong2* hp0 = (const ulonglong2*)(hsm + 32 * w);
    const ulonglong2* hp1 = (const ulonglong2*)(hsm + R + 32 * w);
    const ulonglong2* Wp  = (const ulonglong2*)(Wsm + (size_t)w * NSP * R);
    const float2* xv0 = (const float2*)(xsm);             // batch b0
    const float2* xv1 = (const float2*)(xsm + T * C);     // batch b0+1
    float* __restrict__ o0 = out + (size_t)b0 * T * R + tid;
    float* __restrict__ o1 = out + (size_t)(b0 + 1) * T * R + tid;

    for (int t = 0; t < T; ++t) {
        float* redc = (t & 1) ? red1 : red0;   // ping-pong partials buffer

        // x loads issued at loop top: latency fully hidden under phase1.
        float2 xa = xv0[3 * t], xb = xv0[3 * t + 1], xc = xv0[3 * t + 2];
        float2 xd = xv1[3 * t], xe = xv1[3 * t + 1], xf = xv1[3 * t + 2];

        // acc[(2g+s)*2 + b] : lanes carry (even-k, odd-k) partials for r(g,s), batch b.
        ull acc[16];
        #pragma unroll
        for (int i = 0; i < 16; ++i) acc[i] = 0;

        // ---- register part: k-pairs 0..9 = h chunks q=0..4
        #pragma unroll
        for (int q = 0; q < 5; ++q) {
            ulonglong2 ha = hp0[q];
            ulonglong2 hb = hp1[q];
            #pragma unroll
            for (int gs = 0; gs < 8; ++gs) {
                fma2(acc[gs * 2 + 0], ha.x, wreg[(2 * q) * 8 + gs]);
                fma2(acc[gs * 2 + 1], hb.x, wreg[(2 * q) * 8 + gs]);
                fma2(acc[gs * 2 + 0], ha.y, wreg[(2 * q + 1) * 8 + gs]);
                fma2(acc[gs * 2 + 1], hb.y, wreg[(2 * q + 1) * 8 + gs]);
            }
        }
        // ---- smem part: h chunks q=5..7 (local pairs 10..15), conflict-free LDS.128
        #pragma unroll
        for (int q = 5; q < 8; ++q) {
            const int j0 = 2 * (q - 5), j1 = j0 + 1;
            ulonglong2 ha = hp0[q];
            ulonglong2 hb = hp1[q];
            #pragma unroll
            for (int g = 0; g < 4; ++g) {
                ulonglong2 wA = Wp[(j0 * R + 64 * g + 2 * l) >> 1];
                ulonglong2 wB = Wp[(j1 * R + 64 * g + 2 * l) >> 1];
                fma2(acc[(2 * g + 0) * 2 + 0], ha.x, wA.x);
                fma2(acc[(2 * g + 1) * 2 + 0], ha.x, wA.y);
                fma2(acc[(2 * g + 0) * 2 + 1], hb.x, wA.x);
                fma2(acc[(2 * g + 1) * 2 + 1], hb.x, wA.y);
                fma2(acc[(2 * g + 0) * 2 + 0], ha.y, wB.x);
                fma2(acc[(2 * g + 1) * 2 + 0], ha.y, wB.y);
                fma2(acc[(2 * g + 0) * 2 + 1], hb.y, wB.x);
                fma2(acc[(2 * g + 1) * 2 + 1], hb.y, wB.y);
            }
        }

        // Publish partials: red[w][2r + b], float4 per g.
        #pragma unroll
        for (int g = 0; g < 4; ++g) {
            int r0 = 64 * g + 2 * l;
            float4 v;
            v.x = sum2(acc[(2 * g + 0) * 2 + 0]);
            v.y = sum2(acc[(2 * g + 0) * 2 + 1]);
            v.z = sum2(acc[(2 * g + 1) * 2 + 0]);
            v.w = sum2(acc[(2 * g + 1) * 2 + 1]);
            *(float4*)&redc[w * 2 * R + 2 * r0] = v;
        }

        // xp PRE-barrier: depends only on xsm/win (no red dependence); fills
        // the STS-drain window and shortens the post-barrier serial tail.
        // Only xp0/xp1 stay live across the bar (acc's 32 regs just died).
        float xp0 = xa.x * win[0] + xa.y * win[1] + xb.x * win[2]
                  + xb.y * win[3] + xc.x * win[4] + xc.y * win[5];
        float xp1 = xd.x * win[0] + xd.y * win[1] + xe.x * win[2]
                  + xe.y * win[3] + xf.x * win[4] + xf.y * win[5];

        __syncthreads();   // partials STS -> phase2 LDS (single block bar per step)

        // ---- phase2: thread tid = r; tree-reduce 8 warps' partials.
        const float2* rp = (const float2*)&redc[2 * tid];
        float2 p0 = rp[0 * R], p1 = rp[1 * R], p2 = rp[2 * R], p3 = rp[3 * R];
        float2 p4 = rp[4 * R], p5 = rp[5 * R], p6 = rp[6 * R], p7 = rp[7 * R];
        float sx = ((p0.x + p1.x) + (p2.x + p3.x)) + ((p4.x + p5.x) + (p6.x + p7.x));
        float sy = ((p0.y + p1.y) + (p2.y + p3.y)) + ((p4.y + p5.y) + (p6.y + p7.y));

        float h0n = tanh_fast(sx + xp0);
        float h1n = tanh_fast(sy + xp1);

        hsm[tid]     = h0n;        // consumed next step ONLY by this thread's own warp
        hsm[R + tid] = h1n;
        o0[(size_t)t * R] = h0n;   // coalesced STG
        o1[(size_t)t * R] = h1n;

        __syncwarp();              // intra-warp visibility of hsm for next step
    }
}

extern "C" void kernel_launch(void* const* d_in, const int* in_sizes, int n_in,
                              void* d_out, int out_size) {
    const float* x     = (const float*)d_in[0];
    const float* W_in  = (const float*)d_in[1];
    const float* W_res = (const float*)d_in[2];
    float* out = (float*)d_out;

    // 96KB (Wsm) + 2KB (hsm) + 32KB (red x2) + 24KB (xsm) = 159744 bytes
    const size_t smem_bytes = (size_t)WSM_ULL * sizeof(ull)
                            + (size_t)2 * R * sizeof(float)
                            + (size_t)2 * REDN * sizeof(float)
                            + (size_t)BC * T * C * sizeof(float);
    cudaFuncSetAttribute(esn_kernel, cudaFuncAttributeMaxDynamicSharedMemorySize,
                         (int)smem_bytes);
    esn_kernel<<<NBLK, R, smem_bytes>>>(x, W_in, W_res, out);
}